// round 13
// baseline (speedup 1.0000x reference)
#include <cuda_runtime.h>
#include <math.h>

#define BB   32
#define PP   21824
#define NCLS 80
#define KTOP 1000
#define NIT  22   // ceil(PP / 1024)

// ---------------- scratch (static device globals; no allocation) -------------
__device__ float  g_score[BB * PP];
__device__ float4 g_box[BB * PP];
__device__ int    g_selidx[BB * KTOP];
__device__ float  g_mx[BB];
__device__ unsigned      g_keepbits[BB * 32];
__device__ unsigned char g_cls8[BB * 1024];   // padded to 1024/batch

struct Ptrs {
    const float* cls[5];
    const float* cen[5];
    const float* reg[5];
};

// ---- XLA:CPU-style expf: Cephes/Eigen polynomial, strict mul/add (no FMA) ---
__device__ __forceinline__ float xla_expf(float x) {
    x = fminf(x, 88.3762626647950f);
    x = fmaxf(x, -88.3762626647949f);
    float fx = __fadd_rn(__fmul_rn(x, 1.44269504088896341f), 0.5f);
    fx = floorf(fx);
    float tmp = __fmul_rn(fx, 0.693359375f);
    float z   = __fmul_rn(fx, -2.12194440e-4f);
    float xr  = __fsub_rn(x, tmp);
    xr = __fsub_rn(xr, z);
    z  = __fmul_rn(xr, xr);
    float y = 1.9875691500e-4f;
    y = __fadd_rn(__fmul_rn(y, xr), 1.3981999507e-3f);
    y = __fadd_rn(__fmul_rn(y, xr), 8.3334519073e-3f);
    y = __fadd_rn(__fmul_rn(y, xr), 4.1665795894e-2f);
    y = __fadd_rn(__fmul_rn(y, xr), 1.6666665459e-1f);
    y = __fadd_rn(__fmul_rn(y, xr), 5.0000001201e-1f);
    y = __fadd_rn(__fmul_rn(y, z), xr);
    y = __fadd_rn(y, 1.0f);
    int n = (int)fx;
    float p2n = __uint_as_float((unsigned)(n + 127) << 23);
    return __fmul_rn(y, p2n);
}
__device__ __forceinline__ float xla_sigmoid(float x) {
    float e = xla_expf(-x);
    return __fdiv_rn(1.0f, __fadd_rn(1.0f, e));
}

__device__ __forceinline__ void level_of(int p, int& lvl, int& start, int& HW,
                                         int& W, int& S) {
    if      (p < 16384) { lvl = 0; start = 0;     HW = 16384; W = 128; S = 8;   }
    else if (p < 20480) { lvl = 1; start = 16384; HW = 4096;  W = 64;  S = 16;  }
    else if (p < 21504) { lvl = 2; start = 20480; HW = 1024;  W = 32;  S = 32;  }
    else if (p < 21760) { lvl = 3; start = 21504; HW = 256;   W = 16;  S = 64;  }
    else                { lvl = 4; start = 21760; HW = 64;    W = 8;   S = 128; }
}

// ---------------- kernel 1: streaming max / score / box decode ---------------
__global__ void score_kernel(Ptrs ps) {
    const int Q = (BB * PP) / 4;
    int gid = blockIdx.x * blockDim.x + threadIdx.x;
    if (gid >= Q) return;
    const int per = PP / 4;
    int b = gid / per;
    int p = (gid - b * per) * 4;

    int lvl, start, HW, W, S;
    level_of(p, lvl, start, HW, W, S);
    int local = p - start;
    int hw4 = HW >> 2, l4 = local >> 2;

    const float4* cls = (const float4*)ps.cls[lvl];
    const float4* cp = cls + (b * NCLS) * hw4 + l4;
    float4 mx = cp[0];
#pragma unroll 8
    for (int c = 1; c < NCLS; c++) {
        float4 v = cp[c * hw4];
        mx.x = fmaxf(mx.x, v.x);
        mx.y = fmaxf(mx.y, v.y);
        mx.z = fmaxf(mx.z, v.z);
        mx.w = fmaxf(mx.w, v.w);
    }
    float4 cen = ((const float4*)ps.cen[lvl])[b * hw4 + l4];
    const float4* rg = (const float4*)ps.reg[lvl];
    int rbase = (b * 4) * hw4 + l4;
    float4 rl = rg[rbase], rt = rg[rbase + hw4];
    float4 rr = rg[rbase + 2 * hw4], rb = rg[rbase + 3 * hw4];

    float mxv[4]  = { mx.x, mx.y, mx.z, mx.w };
    float cenv[4] = { cen.x, cen.y, cen.z, cen.w };
    float lv[4] = { rl.x, rl.y, rl.z, rl.w };
    float tv[4] = { rt.x, rt.y, rt.z, rt.w };
    float rv[4] = { rr.x, rr.y, rr.z, rr.w };
    float bv[4] = { rb.x, rb.y, rb.z, rb.w };

    float sco[4];
#pragma unroll
    for (int k = 0; k < 4; k++) {
        int pp = local + k;
        int y = pp / W, x = pp - y * W;
        float cx = (float)(x * S + (S >> 1));
        float cy = (float)(y * S + (S >> 1));
        sco[k] = sqrtf(__fmul_rn(xla_sigmoid(mxv[k]), xla_sigmoid(cenv[k])));
        g_box[b * PP + p + k] = make_float4(cx - lv[k], cy - tv[k], cx + rv[k], cy + bv[k]);
    }
    *(float4*)(g_score + b * PP + p) = make_float4(sco[0], sco[1], sco[2], sco[3]);
}

// ---------------- hybrid bitonic sort (register stages for j<=16) ------------
__device__ __forceinline__ unsigned long long bx64(unsigned long long v, int j,
                                                   int k, int tid) {
    unsigned long long o = __shfl_xor_sync(0xFFFFFFFFu, v, j);
    bool takeMax = (((tid & j) == 0) == ((tid & k) == 0));  // desc regions
    return takeMax ? (o > v ? o : v) : (o < v ? o : v);
}
__device__ void sort1024_desc(unsigned long long* a, int tid) {
    unsigned long long v = a[tid];
#pragma unroll
    for (int k = 2; k <= 32; k <<= 1)
#pragma unroll
        for (int j = k >> 1; j >= 1; j >>= 1) v = bx64(v, j, k, tid);
    a[tid] = v;
    __syncthreads();
    for (int k = 64; k <= 1024; k <<= 1) {
        for (int j = k >> 1; j >= 32; j >>= 1) {
            int ixj = tid ^ j;
            if (ixj > tid) {
                unsigned long long x = a[tid], y = a[ixj];
                if (((tid & k) == 0) ? (x < y) : (x > y)) { a[tid] = y; a[ixj] = x; }
            }
            __syncthreads();
        }
        v = a[tid];
#pragma unroll
        for (int j = 16; j >= 1; j >>= 1) v = bx64(v, j, k, tid);
        a[tid] = v;
        __syncthreads();
    }
}

// ---------------- parallel suffix-scan threshold find ------------------------
__device__ void find_threshold(int* hist, int need, int tid, int lane, int wid,
                               int* sscan, int* sT, int* sHistT, int* sGT) {
    int i0 = 2 * tid;
    int v0 = hist[i0], v1 = hist[i0 + 1];
    int sv = v0 + v1;
#pragma unroll
    for (int o = 1; o < 32; o <<= 1) {
        int t = __shfl_down_sync(0xFFFFFFFFu, sv, o);
        if (lane + o < 32) sv += t;
    }
    if (lane == 0) sscan[wid] = sv;
    __syncthreads();
    if (wid == 0) {
        int ws = sscan[lane];
#pragma unroll
        for (int o = 1; o < 32; o <<= 1) {
            int t = __shfl_down_sync(0xFFFFFFFFu, ws, o);
            if (lane + o < 32) ws += t;
        }
        sscan[lane] = ws;
    }
    __syncthreads();
    int higher = (wid < 31) ? sscan[wid + 1] : 0;
    int S0 = sv + higher;
    int S1 = S0 - v0;
    hist[i0] = S0; hist[i0 + 1] = S1;
    __syncthreads();
    int Sn1 = (i0 + 2 < 2048) ? hist[i0 + 2] : 0;
    if (S0 >= need && S1 < need) { *sT = i0;     *sHistT = S0 - S1;  *sGT = S1;  }
    if (S1 >= need && Sn1 < need){ *sT = i0 + 1; *sHistT = S1 - Sn1; *sGT = Sn1; }
    __syncthreads();
}

// ---------------- kernel 2: per-batch radix-select + single sort -------------
__global__ __launch_bounds__(1024) void topk_kernel(float* out) {
    __shared__ unsigned long long selkeys[1024];
    __shared__ int hist[2048];
    __shared__ int sscan[32];
    __shared__ float swmax[32];
    __shared__ int sT1, sT2, sT3, sH, sG1, sG2, sG3, csel;

    const int b = blockIdx.x, tid = threadIdx.x, nt = 1024;
    const int lane = tid & 31, wid = tid >> 5;
    const unsigned lmask = (1u << lane) - 1u;
    const float* sc = g_score + b * PP;

    // load once, reuse across all passes
    unsigned bits[NIT];
#pragma unroll
    for (int it = 0; it < NIT; it++) {
        int p = tid + it * nt;
        bits[it] = (p < PP) ? __float_as_uint(sc[p]) : 0u;
    }

    // level 1: top-11 bits
    for (int i = tid; i < 2048; i += nt) hist[i] = 0;
    __syncthreads();
#pragma unroll
    for (int it = 0; it < NIT; it++) {
        int bin = (int)(bits[it] >> 21);
        unsigned m = __match_any_sync(0xFFFFFFFFu, bin);
        if ((int)(__ffs(m) - 1) == lane) atomicAdd(&hist[bin], __popc(m));
    }
    __syncthreads();
    find_threshold(hist, KTOP, tid, lane, wid, sscan, &sT1, &sH, &sG1);
    const int T1 = sT1;
    unsigned thr = (unsigned)T1 << 21;
    int total = sG1 + sH;

    if (total > 1024) {
        // level 2: bits [20:10] within bin T1
        for (int i = tid; i < 2048; i += nt) hist[i] = 0;
        __syncthreads();
#pragma unroll
        for (int it = 0; it < NIT; it++) {
            bool v = ((int)(bits[it] >> 21) == T1);
            int sub = (int)((bits[it] >> 10) & 2047);
            unsigned bal = __ballot_sync(0xFFFFFFFFu, v);
            if (v) {
                unsigned m = __match_any_sync(bal, sub);
                if ((int)(__ffs(m) - 1) == lane) atomicAdd(&hist[sub], __popc(m));
            }
        }
        __syncthreads();
        find_threshold(hist, KTOP - sG1, tid, lane, wid, sscan, &sT2, &sH, &sG2);
        thr |= (unsigned)sT2 << 10;
        total = sG1 + sG2 + sH;

        if (total > 1024) {
            // level 3: low 10 bits within (T1,T2)
            unsigned pre = thr >> 10;
            for (int i = tid; i < 2048; i += nt) hist[i] = 0;
            __syncthreads();
#pragma unroll
            for (int it = 0; it < NIT; it++) {
                bool v = ((bits[it] >> 10) == pre);
                int low = (int)(bits[it] & 1023);
                unsigned bal = __ballot_sync(0xFFFFFFFFu, v);
                if (v) {
                    unsigned m = __match_any_sync(bal, low);
                    if ((int)(__ffs(m) - 1) == lane) atomicAdd(&hist[low], __popc(m));
                }
            }
            __syncthreads();
            find_threshold(hist, KTOP - sG1 - sG2, tid, lane, wid, sscan,
                           &sT3, &sH, &sG3);
            thr |= (unsigned)sT3;
        }
    }
    if (tid == 0) csel = 0;
    __syncthreads();

    // single compaction: selected iff bits >= thr
#pragma unroll
    for (int it = 0; it < NIT; it++) {
        int p = tid + it * nt;
        bool sel = (p < PP) && (bits[it] >= thr);
        unsigned long long key = ((unsigned long long)bits[it] << 32) |
                                 (unsigned long long)(0xFFFFFFFFu - (unsigned)p);
        unsigned bd = __ballot_sync(0xFFFFFFFFu, sel);
        if (bd) {
            int ldr = __ffs(bd) - 1, base = 0;
            if (lane == ldr) base = atomicAdd(&csel, __popc(bd));
            base = __shfl_sync(0xFFFFFFFFu, base, ldr);
            if (sel) {
                int pos = base + __popc(bd & lmask);
                if (pos < 1024) selkeys[pos] = key;
            }
        }
    }
    __syncthreads();
    if (tid >= min(csel, 1024)) selkeys[tid] = 0ULL;
    __syncthreads();
    sort1024_desc(selkeys, tid);

    // emit sc / bx / selidx / default keep + keep bitmask; batch box max
    float* osc = out;
    float* obx = out + 2 * BB * KTOP;
    float* okp = out + 6 * BB * KTOP;
    unsigned long long key = selkeys[tid];
    float s = __uint_as_float((unsigned)(key >> 32));
    bool kp = (tid < KTOP) && (s >= 0.05f);
    unsigned kb = __ballot_sync(0xFFFFFFFFu, kp);
    if (lane == 0) g_keepbits[b * 32 + wid] = kb;

    float localmax = -1e30f;
    if (tid < KTOP) {
        unsigned idx = 0xFFFFFFFFu - (unsigned)(key & 0xFFFFFFFFu);
        if (idx >= PP) idx = 0;
        float4 bx = g_box[b * PP + (int)idx];
        osc[b * KTOP + tid] = s;
        ((float4*)obx)[b * KTOP + tid] = bx;
        g_selidx[b * KTOP + tid] = (int)idx;
        okp[b * KTOP + tid] = kp ? 1.0f : 0.0f;
        localmax = fmaxf(fmaxf(bx.x, bx.y), fmaxf(bx.z, bx.w));
    }
#pragma unroll
    for (int o = 16; o > 0; o >>= 1)
        localmax = fmaxf(localmax, __shfl_xor_sync(0xFFFFFFFFu, localmax, o));
    if (lane == 0) swmax[wid] = localmax;
    __syncthreads();
    if (wid == 0) {
        float m = swmax[lane];
#pragma unroll
        for (int o = 16; o > 0; o >>= 1)
            m = fmaxf(m, __shfl_xor_sync(0xFFFFFFFFu, m, o));
        if (lane == 0) g_mx[b] = m;
    }
}

// ---------------- kernel 3: full-chip argmax over sigmoid (selected) ---------
__global__ __launch_bounds__(256) void argmax_kernel(Ptrs ps, float* out) {
    int g = blockIdx.x * 8 + (threadIdx.x >> 5);   // one warp per selected point
    const int lane = threadIdx.x & 31;
    if (g >= BB * KTOP) return;
    int b = g / KTOP, i = g - b * KTOP;
    int p = g_selidx[g];
    int lvl, start, HW, W, S;
    level_of(p, lvl, start, HW, W, S);
    int local = p - start;
    const float* base = ps.cls[lvl] + (long)(b * NCLS) * HW + local;

    float l0 = base[(long)lane * HW];
    float l1 = base[(long)(lane + 32) * HW];
    float l2 = (lane < 16) ? base[(long)(lane + 64) * HW] : 0.0f;

    float bestS = xla_sigmoid(l0); int bestC = lane;
    float s1 = xla_sigmoid(l1);
    if (s1 > bestS) { bestS = s1; bestC = lane + 32; }
    if (lane < 16) {
        float s2 = xla_sigmoid(l2);
        if (s2 > bestS) { bestS = s2; bestC = lane + 64; }
    }
#pragma unroll
    for (int o = 16; o > 0; o >>= 1) {
        float oS = __shfl_xor_sync(0xFFFFFFFFu, bestS, o);
        int   oC = __shfl_xor_sync(0xFFFFFFFFu, bestC, o);
        if (oS > bestS || (oS == bestS && oC < bestC)) { bestS = oS; bestC = oC; }
    }
    if (lane == 0) {
        out[BB * KTOP + b * KTOP + i] = (float)(bestC + 1);  // ocl
        g_cls8[b * 1024 + i] = (unsigned char)(bestC + 1);   // packed class byte
    }
}

// ---------------- kernel 4: per-(class,batch) NMS, compact inputs ------------
__global__ __launch_bounds__(256) void nms_kernel(float* out) {
    __shared__ short clist[1024];
    __shared__ int   wcnt[8], wbase[8];
    __shared__ int   sn;
    __shared__ float fx1[1024], fy1[1024], fx2[1024], fy2[1024], fa[1024];
    __shared__ short klist[1024];

    const int c = blockIdx.x, b = blockIdx.y;   // class 0..79, batch 0..31
    const int tid = threadIdx.x, lane = tid & 31, wid = tid >> 5;
    const unsigned lmask = (1u << lane) - 1u;
    const float* obx = out + 2 * BB * KTOP;
    float* okp = out + 6 * BB * KTOP;

    // phase 1: keep bits (broadcast u32) + class bytes; 4 chunks per warp.
    const unsigned char* clsb = g_cls8 + b * 1024;
    const unsigned char cc8 = (unsigned char)(c + 1);
    bool cand[4];
    unsigned flags[4];
    int myn = 0;
#pragma unroll
    for (int s = 0; s < 4; s++) {
        int i = wid * 128 + s * 32 + lane;
        unsigned kw = g_keepbits[b * 32 + wid * 4 + s];   // broadcast load
        unsigned char cv = clsb[i];                        // padded to 1024
        bool cd = (((kw >> lane) & 1u) != 0u) && (cv == cc8);
        cand[s] = cd;
        flags[s] = __ballot_sync(0xFFFFFFFFu, cd);
        myn += __popc(flags[s]);
    }
    if (lane == 0) wcnt[wid] = myn;
    __syncthreads();
    if (wid == 0 && lane < 8) {
        int v = wcnt[lane];
        int x = v;
#pragma unroll
        for (int o = 1; o < 8; o <<= 1) {
            int t = __shfl_up_sync(0xFFu, x, o);
            if (lane >= o) x += t;
        }
        wbase[lane] = x - v;
        if (lane == 7) sn = x;
    }
    __syncthreads();
    const int n = sn;
    if (n <= 1) return;   // default keep already written by topk

    // phase 2: ordered write (rank-ascending across warps/chunks/lanes)
    {
        int base = wbase[wid];
#pragma unroll
        for (int s = 0; s < 4; s++) {
            if (cand[s])
                clist[base + __popc(flags[s] & lmask)] =
                    (short)(wid * 128 + s * 32 + lane);
            base += __popc(flags[s]);
        }
    }
    __syncthreads();

    const float m1 = __fadd_rn(g_mx[b], 1.0f);
    const float off = __fmul_rn(m1, (float)(c + 1));

    if (n <= 32) {
        // register-resident greedy in warp 0: lane t holds candidate t
        if (wid != 0) return;
        int myr = (lane < n) ? (int)clist[lane] : -1;
        float bx1 = 0, by1 = 0, bx2 = 0, by2 = 0, ba = 0;
        if (myr >= 0) {
            float4 bb = ((const float4*)obx)[b * KTOP + myr];
            bx1 = __fadd_rn(bb.x, off); by1 = __fadd_rn(bb.y, off);
            bx2 = __fadd_rn(bb.z, off); by2 = __fadd_rn(bb.w, off);
            ba = __fmul_rn(fmaxf(__fsub_rn(bx2, bx1), 0.f),
                           fmaxf(__fsub_rn(by2, by1), 0.f));
        }
        bool mykeep = false;
        for (int t = 0; t < n; t++) {
            float tx1 = __shfl_sync(0xFFFFFFFFu, bx1, t);
            float ty1 = __shfl_sync(0xFFFFFFFFu, by1, t);
            float tx2 = __shfl_sync(0xFFFFFFFFu, bx2, t);
            float ty2 = __shfl_sync(0xFFFFFFFFu, by2, t);
            float ta  = __shfl_sync(0xFFFFFFFFu, ba, t);
            bool mysup = false;
            if (mykeep) {   // lane kept and lane < t by construction
                float xx1 = fmaxf(bx1, tx1), yy1 = fmaxf(by1, ty1);
                float xx2 = fminf(bx2, tx2), yy2 = fminf(by2, ty2);
                float w = fmaxf(__fsub_rn(xx2, xx1), 0.f);
                float h = fmaxf(__fsub_rn(yy2, yy1), 0.f);
                float inter = __fmul_rn(w, h);
                float den = __fadd_rn(
                    __fsub_rn(__fadd_rn(ba, ta), inter), 1e-9f);
                mysup = (__fdiv_rn(inter, den) > 0.6f);
            }
            bool sup = __any_sync(0xFFFFFFFFu, mysup);
            if (lane == t) mykeep = !sup;
        }
        if (myr >= 0 && !mykeep) okp[b * KTOP + myr] = 0.0f;
        return;
    }

    // fallback (rare, n>32): stage offset boxes in shared, chunked greedy
    for (int t = tid; t < n; t += 256) {
        int r = (int)clist[t];
        float4 bb = ((const float4*)obx)[b * KTOP + r];
        float x1 = __fadd_rn(bb.x, off), y1 = __fadd_rn(bb.y, off);
        float x2 = __fadd_rn(bb.z, off), y2 = __fadd_rn(bb.w, off);
        fx1[t] = x1; fy1[t] = y1; fx2[t] = x2; fy2[t] = y2;
        fa[t] = __fmul_rn(fmaxf(__fsub_rn(x2, x1), 0.f),
                          fmaxf(__fsub_rn(y2, y1), 0.f));
    }
    __syncthreads();
    if (wid == 0) {
        int nk = 0;
        for (int t = 0; t < n; t++) {
            float ax1 = fx1[t], ay1 = fy1[t], ax2 = fx2[t], ay2 = fy2[t];
            float aa = fa[t];
            bool sup = false;
            for (int kb = 0; kb < nk && !sup; kb += 32) {
                int kk = kb + lane;
                bool mysup = false;
                if (kk < nk) {
                    int j = (int)klist[kk];
                    float xx1 = fmaxf(ax1, fx1[j]), yy1 = fmaxf(ay1, fy1[j]);
                    float xx2 = fminf(ax2, fx2[j]), yy2 = fminf(ay2, fy2[j]);
                    float w = fmaxf(__fsub_rn(xx2, xx1), 0.f);
                    float h = fmaxf(__fsub_rn(yy2, yy1), 0.f);
                    float inter = __fmul_rn(w, h);
                    float den = __fadd_rn(
                        __fsub_rn(__fadd_rn(aa, fa[j]), inter), 1e-9f);
                    mysup = (__fdiv_rn(inter, den) > 0.6f);
                }
                if (__any_sync(0xFFFFFFFFu, mysup)) sup = true;
            }
            if (sup) {
                if (lane == 0) okp[b * KTOP + (int)clist[t]] = 0.0f;
            } else {
                if (lane == 0) klist[nk] = (short)t;
                nk++;
            }
            __syncwarp();
        }
    }
}

// ---------------- launch ------------------------------------------------------
extern "C" void kernel_launch(void* const* d_in, const int* in_sizes, int n_in,
                              void* d_out, int out_size) {
    Ptrs ps;
    for (int i = 0; i < 5; i++) {
        ps.cls[i] = (const float*)d_in[i];
        ps.cen[i] = (const float*)d_in[5 + i];
        ps.reg[i] = (const float*)d_in[10 + i];
    }
    const int Q = (BB * PP) / 4;
    float* out = (float*)d_out;
    score_kernel<<<(Q + 255) / 256, 256>>>(ps);
    topk_kernel<<<BB, 1024>>>(out);
    argmax_kernel<<<(BB * KTOP + 7) / 8, 256>>>(ps, out);
    dim3 ng(NCLS, BB);
    nms_kernel<<<ng, 256>>>(out);
}

// round 14
// speedup vs baseline: 1.0464x; 1.0464x over previous
#include <cuda_runtime.h>
#include <math.h>

#define BB   32
#define PP   21824
#define NCLS 80
#define KTOP 1000
#define NIT  22   // ceil(PP / 1024)

// ---------------- scratch (static device globals; no allocation) -------------
__device__ float  g_score[BB * PP];
__device__ float4 g_box[BB * PP];
__device__ int    g_selidx[BB * KTOP];
__device__ float  g_mx[BB];
__device__ unsigned      g_keepbits[BB * 32];
__device__ unsigned char g_cls8[BB * 1024];   // padded to 1024/batch

struct Ptrs {
    const float* cls[5];
    const float* cen[5];
    const float* reg[5];
};

// ---- XLA:CPU-style expf: Cephes/Eigen polynomial, strict mul/add (no FMA) ---
__device__ __forceinline__ float xla_expf(float x) {
    x = fminf(x, 88.3762626647950f);
    x = fmaxf(x, -88.3762626647949f);
    float fx = __fadd_rn(__fmul_rn(x, 1.44269504088896341f), 0.5f);
    fx = floorf(fx);
    float tmp = __fmul_rn(fx, 0.693359375f);
    float z   = __fmul_rn(fx, -2.12194440e-4f);
    float xr  = __fsub_rn(x, tmp);
    xr = __fsub_rn(xr, z);
    z  = __fmul_rn(xr, xr);
    float y = 1.9875691500e-4f;
    y = __fadd_rn(__fmul_rn(y, xr), 1.3981999507e-3f);
    y = __fadd_rn(__fmul_rn(y, xr), 8.3334519073e-3f);
    y = __fadd_rn(__fmul_rn(y, xr), 4.1665795894e-2f);
    y = __fadd_rn(__fmul_rn(y, xr), 1.6666665459e-1f);
    y = __fadd_rn(__fmul_rn(y, xr), 5.0000001201e-1f);
    y = __fadd_rn(__fmul_rn(y, z), xr);
    y = __fadd_rn(y, 1.0f);
    int n = (int)fx;
    float p2n = __uint_as_float((unsigned)(n + 127) << 23);
    return __fmul_rn(y, p2n);
}
__device__ __forceinline__ float xla_sigmoid(float x) {
    float e = xla_expf(-x);
    return __fdiv_rn(1.0f, __fadd_rn(1.0f, e));
}

__device__ __forceinline__ void level_of(int p, int& lvl, int& start, int& HW,
                                         int& W, int& S) {
    if      (p < 16384) { lvl = 0; start = 0;     HW = 16384; W = 128; S = 8;   }
    else if (p < 20480) { lvl = 1; start = 16384; HW = 4096;  W = 64;  S = 16;  }
    else if (p < 21504) { lvl = 2; start = 20480; HW = 1024;  W = 32;  S = 32;  }
    else if (p < 21760) { lvl = 3; start = 21504; HW = 256;   W = 16;  S = 64;  }
    else                { lvl = 4; start = 21760; HW = 64;    W = 8;   S = 128; }
}

// ---------------- kernel 1: streaming max / score / box decode ---------------
__global__ void score_kernel(Ptrs ps) {
    const int Q = (BB * PP) / 4;
    int gid = blockIdx.x * blockDim.x + threadIdx.x;
    if (gid >= Q) return;
    const int per = PP / 4;
    int b = gid / per;
    int p = (gid - b * per) * 4;

    int lvl, start, HW, W, S;
    level_of(p, lvl, start, HW, W, S);
    int local = p - start;
    int hw4 = HW >> 2, l4 = local >> 2;

    const float4* cls = (const float4*)ps.cls[lvl];
    const float4* cp = cls + (b * NCLS) * hw4 + l4;
    float4 mx = cp[0];
#pragma unroll 8
    for (int c = 1; c < NCLS; c++) {
        float4 v = cp[c * hw4];
        mx.x = fmaxf(mx.x, v.x);
        mx.y = fmaxf(mx.y, v.y);
        mx.z = fmaxf(mx.z, v.z);
        mx.w = fmaxf(mx.w, v.w);
    }
    float4 cen = ((const float4*)ps.cen[lvl])[b * hw4 + l4];
    const float4* rg = (const float4*)ps.reg[lvl];
    int rbase = (b * 4) * hw4 + l4;
    float4 rl = rg[rbase], rt = rg[rbase + hw4];
    float4 rr = rg[rbase + 2 * hw4], rb = rg[rbase + 3 * hw4];

    float mxv[4]  = { mx.x, mx.y, mx.z, mx.w };
    float cenv[4] = { cen.x, cen.y, cen.z, cen.w };
    float lv[4] = { rl.x, rl.y, rl.z, rl.w };
    float tv[4] = { rt.x, rt.y, rt.z, rt.w };
    float rv[4] = { rr.x, rr.y, rr.z, rr.w };
    float bv[4] = { rb.x, rb.y, rb.z, rb.w };

    float sco[4];
#pragma unroll
    for (int k = 0; k < 4; k++) {
        int pp = local + k;
        int y = pp / W, x = pp - y * W;
        float cx = (float)(x * S + (S >> 1));
        float cy = (float)(y * S + (S >> 1));
        sco[k] = sqrtf(__fmul_rn(xla_sigmoid(mxv[k]), xla_sigmoid(cenv[k])));
        g_box[b * PP + p + k] = make_float4(cx - lv[k], cy - tv[k], cx + rv[k], cy + bv[k]);
    }
    *(float4*)(g_score + b * PP + p) = make_float4(sco[0], sco[1], sco[2], sco[3]);
}

// ---------------- hybrid bitonic sort (register stages for j<=16) ------------
__device__ __forceinline__ unsigned long long bx64(unsigned long long v, int j,
                                                   int k, int tid) {
    unsigned long long o = __shfl_xor_sync(0xFFFFFFFFu, v, j);
    bool takeMax = (((tid & j) == 0) == ((tid & k) == 0));  // desc regions
    return takeMax ? (o > v ? o : v) : (o < v ? o : v);
}
__device__ void sort1024_desc(unsigned long long* a, int tid) {
    unsigned long long v = a[tid];
#pragma unroll
    for (int k = 2; k <= 32; k <<= 1)
#pragma unroll
        for (int j = k >> 1; j >= 1; j >>= 1) v = bx64(v, j, k, tid);
    a[tid] = v;
    __syncthreads();
    for (int k = 64; k <= 1024; k <<= 1) {
        for (int j = k >> 1; j >= 32; j >>= 1) {
            int ixj = tid ^ j;
            if (ixj > tid) {
                unsigned long long x = a[tid], y = a[ixj];
                if (((tid & k) == 0) ? (x < y) : (x > y)) { a[tid] = y; a[ixj] = x; }
            }
            __syncthreads();
        }
        v = a[tid];
#pragma unroll
        for (int j = 16; j >= 1; j >>= 1) v = bx64(v, j, k, tid);
        a[tid] = v;
        __syncthreads();
    }
}

// ---------------- parallel suffix-scan threshold find ------------------------
__device__ void find_threshold(int* hist, int need, int tid, int lane, int wid,
                               int* sscan, int* sT, int* sHistT, int* sGT) {
    int i0 = 2 * tid;
    int v0 = hist[i0], v1 = hist[i0 + 1];
    int sv = v0 + v1;
#pragma unroll
    for (int o = 1; o < 32; o <<= 1) {
        int t = __shfl_down_sync(0xFFFFFFFFu, sv, o);
        if (lane + o < 32) sv += t;
    }
    if (lane == 0) sscan[wid] = sv;
    __syncthreads();
    if (wid == 0) {
        int ws = sscan[lane];
#pragma unroll
        for (int o = 1; o < 32; o <<= 1) {
            int t = __shfl_down_sync(0xFFFFFFFFu, ws, o);
            if (lane + o < 32) ws += t;
        }
        sscan[lane] = ws;
    }
    __syncthreads();
    int higher = (wid < 31) ? sscan[wid + 1] : 0;
    int S0 = sv + higher;
    int S1 = S0 - v0;
    hist[i0] = S0; hist[i0 + 1] = S1;
    __syncthreads();
    int Sn1 = (i0 + 2 < 2048) ? hist[i0 + 2] : 0;
    if (S0 >= need && S1 < need) { *sT = i0;     *sHistT = S0 - S1;  *sGT = S1;  }
    if (S1 >= need && Sn1 < need){ *sT = i0 + 1; *sHistT = S1 - Sn1; *sGT = Sn1; }
    __syncthreads();
}

// ---------------- kernel 2: per-batch radix-select + single sort -------------
__global__ __launch_bounds__(1024) void topk_kernel(float* out) {
    __shared__ unsigned long long selkeys[1024];
    __shared__ int hist[2048];
    __shared__ int sscan[32];
    __shared__ float swmax[32];
    __shared__ int sT1, sT2, sT3, sH, sG1, sG2, sG3, csel;

    const int b = blockIdx.x, tid = threadIdx.x, nt = 1024;
    const int lane = tid & 31, wid = tid >> 5;
    const unsigned lmask = (1u << lane) - 1u;
    const float* sc = g_score + b * PP;

    // load once, reuse across all passes
    unsigned bits[NIT];
#pragma unroll
    for (int it = 0; it < NIT; it++) {
        int p = tid + it * nt;
        bits[it] = (p < PP) ? __float_as_uint(sc[p]) : 0u;
    }

    // level 1: top-11 bits
    for (int i = tid; i < 2048; i += nt) hist[i] = 0;
    __syncthreads();
#pragma unroll
    for (int it = 0; it < NIT; it++) {
        int bin = (int)(bits[it] >> 21);
        unsigned m = __match_any_sync(0xFFFFFFFFu, bin);
        if ((int)(__ffs(m) - 1) == lane) atomicAdd(&hist[bin], __popc(m));
    }
    __syncthreads();
    find_threshold(hist, KTOP, tid, lane, wid, sscan, &sT1, &sH, &sG1);
    const int T1 = sT1;
    unsigned thr = (unsigned)T1 << 21;
    int total = sG1 + sH;

    if (total > 1024) {
        // level 2: bits [20:10] within bin T1
        for (int i = tid; i < 2048; i += nt) hist[i] = 0;
        __syncthreads();
#pragma unroll
        for (int it = 0; it < NIT; it++) {
            bool v = ((int)(bits[it] >> 21) == T1);
            int sub = (int)((bits[it] >> 10) & 2047);
            unsigned bal = __ballot_sync(0xFFFFFFFFu, v);
            if (v) {
                unsigned m = __match_any_sync(bal, sub);
                if ((int)(__ffs(m) - 1) == lane) atomicAdd(&hist[sub], __popc(m));
            }
        }
        __syncthreads();
        find_threshold(hist, KTOP - sG1, tid, lane, wid, sscan, &sT2, &sH, &sG2);
        thr |= (unsigned)sT2 << 10;
        total = sG1 + sG2 + sH;

        if (total > 1024) {
            // level 3: low 10 bits within (T1,T2)
            unsigned pre = thr >> 10;
            for (int i = tid; i < 2048; i += nt) hist[i] = 0;
            __syncthreads();
#pragma unroll
            for (int it = 0; it < NIT; it++) {
                bool v = ((bits[it] >> 10) == pre);
                int low = (int)(bits[it] & 1023);
                unsigned bal = __ballot_sync(0xFFFFFFFFu, v);
                if (v) {
                    unsigned m = __match_any_sync(bal, low);
                    if ((int)(__ffs(m) - 1) == lane) atomicAdd(&hist[low], __popc(m));
                }
            }
            __syncthreads();
            find_threshold(hist, KTOP - sG1 - sG2, tid, lane, wid, sscan,
                           &sT3, &sH, &sG3);
            thr |= (unsigned)sT3;
        }
    }
    if (tid == 0) csel = 0;
    __syncthreads();

    // single compaction: selected iff bits >= thr
#pragma unroll
    for (int it = 0; it < NIT; it++) {
        int p = tid + it * nt;
        bool sel = (p < PP) && (bits[it] >= thr);
        unsigned long long key = ((unsigned long long)bits[it] << 32) |
                                 (unsigned long long)(0xFFFFFFFFu - (unsigned)p);
        unsigned bd = __ballot_sync(0xFFFFFFFFu, sel);
        if (bd) {
            int ldr = __ffs(bd) - 1, base = 0;
            if (lane == ldr) base = atomicAdd(&csel, __popc(bd));
            base = __shfl_sync(0xFFFFFFFFu, base, ldr);
            if (sel) {
                int pos = base + __popc(bd & lmask);
                if (pos < 1024) selkeys[pos] = key;
            }
        }
    }
    __syncthreads();
    if (tid >= min(csel, 1024)) selkeys[tid] = 0ULL;
    __syncthreads();
    sort1024_desc(selkeys, tid);

    // emit sc / bx / selidx / default keep + keep bitmask; batch box max
    float* osc = out;
    float* obx = out + 2 * BB * KTOP;
    float* okp = out + 6 * BB * KTOP;
    unsigned long long key = selkeys[tid];
    float s = __uint_as_float((unsigned)(key >> 32));
    bool kp = (tid < KTOP) && (s >= 0.05f);
    unsigned kb = __ballot_sync(0xFFFFFFFFu, kp);
    if (lane == 0) g_keepbits[b * 32 + wid] = kb;

    float localmax = -1e30f;
    if (tid < KTOP) {
        unsigned idx = 0xFFFFFFFFu - (unsigned)(key & 0xFFFFFFFFu);
        if (idx >= PP) idx = 0;
        float4 bx = g_box[b * PP + (int)idx];
        osc[b * KTOP + tid] = s;
        ((float4*)obx)[b * KTOP + tid] = bx;
        g_selidx[b * KTOP + tid] = (int)idx;
        okp[b * KTOP + tid] = kp ? 1.0f : 0.0f;
        localmax = fmaxf(fmaxf(bx.x, bx.y), fmaxf(bx.z, bx.w));
    }
#pragma unroll
    for (int o = 16; o > 0; o >>= 1)
        localmax = fmaxf(localmax, __shfl_xor_sync(0xFFFFFFFFu, localmax, o));
    if (lane == 0) swmax[wid] = localmax;
    __syncthreads();
    if (wid == 0) {
        float m = swmax[lane];
#pragma unroll
        for (int o = 16; o > 0; o >>= 1)
            m = fmaxf(m, __shfl_xor_sync(0xFFFFFFFFu, m, o));
        if (lane == 0) g_mx[b] = m;
    }
}

// ---------------- kernel 3: full-chip argmax over sigmoid (selected) ---------
__global__ __launch_bounds__(256) void argmax_kernel(Ptrs ps, float* out) {
    int g = blockIdx.x * 8 + (threadIdx.x >> 5);   // one warp per selected point
    const int lane = threadIdx.x & 31;
    if (g >= BB * KTOP) return;
    int b = g / KTOP, i = g - b * KTOP;
    int p = g_selidx[g];
    int lvl, start, HW, W, S;
    level_of(p, lvl, start, HW, W, S);
    int local = p - start;
    const float* base = ps.cls[lvl] + (long)(b * NCLS) * HW + local;

    float l0 = base[(long)lane * HW];
    float l1 = base[(long)(lane + 32) * HW];
    float l2 = (lane < 16) ? base[(long)(lane + 64) * HW] : 0.0f;

    float bestS = xla_sigmoid(l0); int bestC = lane;
    float s1 = xla_sigmoid(l1);
    if (s1 > bestS) { bestS = s1; bestC = lane + 32; }
    if (lane < 16) {
        float s2 = xla_sigmoid(l2);
        if (s2 > bestS) { bestS = s2; bestC = lane + 64; }
    }
#pragma unroll
    for (int o = 16; o > 0; o >>= 1) {
        float oS = __shfl_xor_sync(0xFFFFFFFFu, bestS, o);
        int   oC = __shfl_xor_sync(0xFFFFFFFFu, bestC, o);
        if (oS > bestS || (oS == bestS && oC < bestC)) { bestS = oS; bestC = oC; }
    }
    if (lane == 0) {
        out[BB * KTOP + b * KTOP + i] = (float)(bestC + 1);  // ocl
        g_cls8[b * 1024 + i] = (unsigned char)(bestC + 1);   // packed class byte
    }
}

// ---------------- kernel 4: warp-per-(batch,class) NMS -----------------------
// 2560 (b,c) pairs, one WARP each: 320 blocks x 8 warps. No block barriers on
// the fast path; candidate enumeration is 32 ballot rounds + __fns.
__global__ __launch_bounds__(256) void nms_kernel(float* out) {
    __shared__ short wclist[8][1024];   // fallback only
    __shared__ short wklist[8][1024];   // fallback only

    const int tid = threadIdx.x, lane = tid & 31, wid = tid >> 5;
    const unsigned lmask = (1u << lane) - 1u;
    const int pair = blockIdx.x * 8 + wid;      // 0..2559
    const int b = pair / NCLS, c = pair - b * NCLS;
    const float* obx = out + 2 * BB * KTOP;
    float* okp = out + 6 * BB * KTOP;

    const unsigned char* clsb = g_cls8 + b * 1024;
    const unsigned char cc8 = (unsigned char)(c + 1);
    const unsigned kw = g_keepbits[b * 32 + lane];   // lane's keep word

    // prefetch this lane's 32 class bytes (rank = s*32 + lane), one MLP batch
    unsigned char cvs[32];
#pragma unroll
    for (int s = 0; s < 32; s++) cvs[s] = clsb[s * 32 + lane];

    // enumerate candidates in rank order; lane t receives candidate t's rank
    int nk = 0, myrank = -1;
#pragma unroll
    for (int s = 0; s < 32; s++) {
        unsigned kws = __shfl_sync(0xFFFFFFFFu, kw, s);
        bool cd = (((kws >> lane) & 1u) != 0u) && (cvs[s] == cc8);
        unsigned bal = __ballot_sync(0xFFFFFFFFu, cd);
        int cnt = __popc(bal);
        int rel = lane - nk;
        if (rel >= 0 && rel < cnt) myrank = s * 32 + (int)__fns(bal, 0, rel + 1);
        nk += cnt;
    }
    const int n = nk;
    if (n <= 1) return;   // default keep already written by topk

    const float m1 = __fadd_rn(g_mx[b], 1.0f);
    const float off = __fmul_rn(m1, (float)(c + 1));

    if (n <= 32) {
        // register-resident greedy: lane t holds candidate t
        int myr = (lane < n) ? myrank : -1;
        float bx1 = 0, by1 = 0, bx2 = 0, by2 = 0, ba = 0;
        if (myr >= 0) {
            float4 bb = ((const float4*)obx)[b * KTOP + myr];
            bx1 = __fadd_rn(bb.x, off); by1 = __fadd_rn(bb.y, off);
            bx2 = __fadd_rn(bb.z, off); by2 = __fadd_rn(bb.w, off);
            ba = __fmul_rn(fmaxf(__fsub_rn(bx2, bx1), 0.f),
                           fmaxf(__fsub_rn(by2, by1), 0.f));
        }
        bool mykeep = false;
        for (int t = 0; t < n; t++) {
            float tx1 = __shfl_sync(0xFFFFFFFFu, bx1, t);
            float ty1 = __shfl_sync(0xFFFFFFFFu, by1, t);
            float tx2 = __shfl_sync(0xFFFFFFFFu, bx2, t);
            float ty2 = __shfl_sync(0xFFFFFFFFu, by2, t);
            float ta  = __shfl_sync(0xFFFFFFFFu, ba, t);
            bool mysup = false;
            if (mykeep) {   // lane kept and lane < t by construction
                float xx1 = fmaxf(bx1, tx1), yy1 = fmaxf(by1, ty1);
                float xx2 = fminf(bx2, tx2), yy2 = fminf(by2, ty2);
                float w = fmaxf(__fsub_rn(xx2, xx1), 0.f);
                float h = fmaxf(__fsub_rn(yy2, yy1), 0.f);
                float inter = __fmul_rn(w, h);
                float den = __fadd_rn(
                    __fsub_rn(__fadd_rn(ba, ta), inter), 1e-9f);
                mysup = (__fdiv_rn(inter, den) > 0.6f);
            }
            bool sup = __any_sync(0xFFFFFFFFu, mysup);
            if (lane == t) mykeep = !sup;
        }
        if (myr >= 0 && !mykeep) okp[b * KTOP + myr] = 0.0f;
        return;
    }

    // fallback (rare, n>32): re-scan ranks into per-warp smem, chunked greedy
    {
        int pos = 0;
#pragma unroll
        for (int s = 0; s < 32; s++) {
            unsigned kws = __shfl_sync(0xFFFFFFFFu, kw, s);
            bool cd = (((kws >> lane) & 1u) != 0u) && (cvs[s] == cc8);
            unsigned bal = __ballot_sync(0xFFFFFFFFu, cd);
            if (cd) wclist[wid][pos + __popc(bal & lmask)] = (short)(s * 32 + lane);
            pos += __popc(bal);
        }
        __syncwarp();
        int nkk = 0;
        for (int t = 0; t < n; t++) {
            int r = (int)wclist[wid][t];
            float4 bbt = ((const float4*)obx)[b * KTOP + r];   // broadcast
            float ax1 = __fadd_rn(bbt.x, off), ay1 = __fadd_rn(bbt.y, off);
            float ax2 = __fadd_rn(bbt.z, off), ay2 = __fadd_rn(bbt.w, off);
            float aa = __fmul_rn(fmaxf(__fsub_rn(ax2, ax1), 0.f),
                                 fmaxf(__fsub_rn(ay2, ay1), 0.f));
            bool sup = false;
            for (int kb = 0; kb < nkk && !sup; kb += 32) {
                int kk = kb + lane;
                bool mysup = false;
                if (kk < nkk) {
                    int j = (int)wklist[wid][kk];
                    float4 bbj = ((const float4*)obx)[b * KTOP + j];
                    float jx1 = __fadd_rn(bbj.x, off), jy1 = __fadd_rn(bbj.y, off);
                    float jx2 = __fadd_rn(bbj.z, off), jy2 = __fadd_rn(bbj.w, off);
                    float ja = __fmul_rn(fmaxf(__fsub_rn(jx2, jx1), 0.f),
                                         fmaxf(__fsub_rn(jy2, jy1), 0.f));
                    float xx1 = fmaxf(ax1, jx1), yy1 = fmaxf(ay1, jy1);
                    float xx2 = fminf(ax2, jx2), yy2 = fminf(ay2, jy2);
                    float w = fmaxf(__fsub_rn(xx2, xx1), 0.f);
                    float h = fmaxf(__fsub_rn(yy2, yy1), 0.f);
                    float inter = __fmul_rn(w, h);
                    float den = __fadd_rn(
                        __fsub_rn(__fadd_rn(aa, ja), inter), 1e-9f);
                    mysup = (__fdiv_rn(inter, den) > 0.6f);
                }
                if (__any_sync(0xFFFFFFFFu, mysup)) sup = true;
            }
            if (sup) {
                if (lane == 0) okp[b * KTOP + r] = 0.0f;
            } else {
                if (lane == 0) wklist[wid][nkk] = (short)r;
                nkk++;
            }
            __syncwarp();
        }
    }
}

// ---------------- launch ------------------------------------------------------
extern "C" void kernel_launch(void* const* d_in, const int* in_sizes, int n_in,
                              void* d_out, int out_size) {
    Ptrs ps;
    for (int i = 0; i < 5; i++) {
        ps.cls[i] = (const float*)d_in[i];
        ps.cen[i] = (const float*)d_in[5 + i];
        ps.reg[i] = (const float*)d_in[10 + i];
    }
    const int Q = (BB * PP) / 4;
    float* out = (float*)d_out;
    score_kernel<<<(Q + 255) / 256, 256>>>(ps);
    topk_kernel<<<BB, 1024>>>(out);
    argmax_kernel<<<(BB * KTOP + 7) / 8, 256>>>(ps, out);
    nms_kernel<<<(BB * NCLS) / 8, 256>>>(out);
}

// round 15
// speedup vs baseline: 1.0505x; 1.0039x over previous
#include <cuda_runtime.h>
#include <math.h>

#define BB   32
#define PP   21824
#define NCLS 80
#define KTOP 1000
#define NIT  22   // ceil(PP / 1024)

// ---------------- scratch (static device globals; no allocation) -------------
__device__ float  g_score[BB * PP];
__device__ float4 g_box[BB * PP];
__device__ int    g_selidx[BB * KTOP];
__device__ float  g_mx[BB];
__device__ unsigned      g_keepbits[BB * 32];
__device__ unsigned char g_cls8[BB * 1024];    // TRANSPOSED: [(i&31)*32 + (i>>5)]
__device__ short  g_fclist[BB * NCLS * KTOP];  // fallback (n>32) scratch
__device__ short  g_fklist[BB * NCLS * KTOP];

struct Ptrs {
    const float* cls[5];
    const float* cen[5];
    const float* reg[5];
};

// ---- XLA:CPU-style expf: Cephes/Eigen polynomial, strict mul/add (no FMA) ---
__device__ __forceinline__ float xla_expf(float x) {
    x = fminf(x, 88.3762626647950f);
    x = fmaxf(x, -88.3762626647949f);
    float fx = __fadd_rn(__fmul_rn(x, 1.44269504088896341f), 0.5f);
    fx = floorf(fx);
    float tmp = __fmul_rn(fx, 0.693359375f);
    float z   = __fmul_rn(fx, -2.12194440e-4f);
    float xr  = __fsub_rn(x, tmp);
    xr = __fsub_rn(xr, z);
    z  = __fmul_rn(xr, xr);
    float y = 1.9875691500e-4f;
    y = __fadd_rn(__fmul_rn(y, xr), 1.3981999507e-3f);
    y = __fadd_rn(__fmul_rn(y, xr), 8.3334519073e-3f);
    y = __fadd_rn(__fmul_rn(y, xr), 4.1665795894e-2f);
    y = __fadd_rn(__fmul_rn(y, xr), 1.6666665459e-1f);
    y = __fadd_rn(__fmul_rn(y, xr), 5.0000001201e-1f);
    y = __fadd_rn(__fmul_rn(y, z), xr);
    y = __fadd_rn(y, 1.0f);
    int n = (int)fx;
    float p2n = __uint_as_float((unsigned)(n + 127) << 23);
    return __fmul_rn(y, p2n);
}
__device__ __forceinline__ float xla_sigmoid(float x) {
    float e = xla_expf(-x);
    return __fdiv_rn(1.0f, __fadd_rn(1.0f, e));
}

__device__ __forceinline__ void level_of(int p, int& lvl, int& start, int& HW,
                                         int& W, int& S) {
    if      (p < 16384) { lvl = 0; start = 0;     HW = 16384; W = 128; S = 8;   }
    else if (p < 20480) { lvl = 1; start = 16384; HW = 4096;  W = 64;  S = 16;  }
    else if (p < 21504) { lvl = 2; start = 20480; HW = 1024;  W = 32;  S = 32;  }
    else if (p < 21760) { lvl = 3; start = 21504; HW = 256;   W = 16;  S = 64;  }
    else                { lvl = 4; start = 21760; HW = 64;    W = 8;   S = 128; }
}

// ---------------- kernel 1: streaming max / score / box decode ---------------
__global__ void score_kernel(Ptrs ps) {
    const int Q = (BB * PP) / 4;
    int gid = blockIdx.x * blockDim.x + threadIdx.x;
    if (gid >= Q) return;
    const int per = PP / 4;
    int b = gid / per;
    int p = (gid - b * per) * 4;

    int lvl, start, HW, W, S;
    level_of(p, lvl, start, HW, W, S);
    int local = p - start;
    int hw4 = HW >> 2, l4 = local >> 2;

    const float4* cls = (const float4*)ps.cls[lvl];
    const float4* cp = cls + (b * NCLS) * hw4 + l4;
    float4 mx = cp[0];
#pragma unroll 8
    for (int c = 1; c < NCLS; c++) {
        float4 v = cp[c * hw4];
        mx.x = fmaxf(mx.x, v.x);
        mx.y = fmaxf(mx.y, v.y);
        mx.z = fmaxf(mx.z, v.z);
        mx.w = fmaxf(mx.w, v.w);
    }
    float4 cen = ((const float4*)ps.cen[lvl])[b * hw4 + l4];
    const float4* rg = (const float4*)ps.reg[lvl];
    int rbase = (b * 4) * hw4 + l4;
    float4 rl = rg[rbase], rt = rg[rbase + hw4];
    float4 rr = rg[rbase + 2 * hw4], rb = rg[rbase + 3 * hw4];

    float mxv[4]  = { mx.x, mx.y, mx.z, mx.w };
    float cenv[4] = { cen.x, cen.y, cen.z, cen.w };
    float lv[4] = { rl.x, rl.y, rl.z, rl.w };
    float tv[4] = { rt.x, rt.y, rt.z, rt.w };
    float rv[4] = { rr.x, rr.y, rr.z, rr.w };
    float bv[4] = { rb.x, rb.y, rb.z, rb.w };

    float sco[4];
#pragma unroll
    for (int k = 0; k < 4; k++) {
        int pp = local + k;
        int y = pp / W, x = pp - y * W;
        float cx = (float)(x * S + (S >> 1));
        float cy = (float)(y * S + (S >> 1));
        sco[k] = sqrtf(__fmul_rn(xla_sigmoid(mxv[k]), xla_sigmoid(cenv[k])));
        g_box[b * PP + p + k] = make_float4(cx - lv[k], cy - tv[k], cx + rv[k], cy + bv[k]);
    }
    *(float4*)(g_score + b * PP + p) = make_float4(sco[0], sco[1], sco[2], sco[3]);
}

// ---------------- hybrid bitonic sort (register stages for j<=16) ------------
__device__ __forceinline__ unsigned long long bx64(unsigned long long v, int j,
                                                   int k, int tid) {
    unsigned long long o = __shfl_xor_sync(0xFFFFFFFFu, v, j);
    bool takeMax = (((tid & j) == 0) == ((tid & k) == 0));  // desc regions
    return takeMax ? (o > v ? o : v) : (o < v ? o : v);
}
__device__ void sort1024_desc(unsigned long long* a, int tid) {
    unsigned long long v = a[tid];
#pragma unroll
    for (int k = 2; k <= 32; k <<= 1)
#pragma unroll
        for (int j = k >> 1; j >= 1; j >>= 1) v = bx64(v, j, k, tid);
    a[tid] = v;
    __syncthreads();
    for (int k = 64; k <= 1024; k <<= 1) {
        for (int j = k >> 1; j >= 32; j >>= 1) {
            int ixj = tid ^ j;
            if (ixj > tid) {
                unsigned long long x = a[tid], y = a[ixj];
                if (((tid & k) == 0) ? (x < y) : (x > y)) { a[tid] = y; a[ixj] = x; }
            }
            __syncthreads();
        }
        v = a[tid];
#pragma unroll
        for (int j = 16; j >= 1; j >>= 1) v = bx64(v, j, k, tid);
        a[tid] = v;
        __syncthreads();
    }
}

// ---------------- parallel suffix-scan threshold find ------------------------
__device__ void find_threshold(int* hist, int need, int tid, int lane, int wid,
                               int* sscan, int* sT, int* sHistT, int* sGT) {
    int i0 = 2 * tid;
    int v0 = hist[i0], v1 = hist[i0 + 1];
    int sv = v0 + v1;
#pragma unroll
    for (int o = 1; o < 32; o <<= 1) {
        int t = __shfl_down_sync(0xFFFFFFFFu, sv, o);
        if (lane + o < 32) sv += t;
    }
    if (lane == 0) sscan[wid] = sv;
    __syncthreads();
    if (wid == 0) {
        int ws = sscan[lane];
#pragma unroll
        for (int o = 1; o < 32; o <<= 1) {
            int t = __shfl_down_sync(0xFFFFFFFFu, ws, o);
            if (lane + o < 32) ws += t;
        }
        sscan[lane] = ws;
    }
    __syncthreads();
    int higher = (wid < 31) ? sscan[wid + 1] : 0;
    int S0 = sv + higher;
    int S1 = S0 - v0;
    hist[i0] = S0; hist[i0 + 1] = S1;
    __syncthreads();
    int Sn1 = (i0 + 2 < 2048) ? hist[i0 + 2] : 0;
    if (S0 >= need && S1 < need) { *sT = i0;     *sHistT = S0 - S1;  *sGT = S1;  }
    if (S1 >= need && Sn1 < need){ *sT = i0 + 1; *sHistT = S1 - Sn1; *sGT = Sn1; }
    __syncthreads();
}

// ---------------- kernel 2: per-batch radix-select + single sort -------------
__global__ __launch_bounds__(1024) void topk_kernel(float* out) {
    __shared__ unsigned long long selkeys[1024];
    __shared__ int hist[2048];
    __shared__ int sscan[32];
    __shared__ float swmax[32];
    __shared__ int sT1, sT2, sT3, sH, sG1, sG2, sG3, csel;

    const int b = blockIdx.x, tid = threadIdx.x, nt = 1024;
    const int lane = tid & 31, wid = tid >> 5;
    const unsigned lmask = (1u << lane) - 1u;
    const float* sc = g_score + b * PP;

    // load once, reuse across all passes
    unsigned bits[NIT];
#pragma unroll
    for (int it = 0; it < NIT; it++) {
        int p = tid + it * nt;
        bits[it] = (p < PP) ? __float_as_uint(sc[p]) : 0u;
    }

    // level 1: top-11 bits
    for (int i = tid; i < 2048; i += nt) hist[i] = 0;
    __syncthreads();
#pragma unroll
    for (int it = 0; it < NIT; it++) {
        int bin = (int)(bits[it] >> 21);
        unsigned m = __match_any_sync(0xFFFFFFFFu, bin);
        if ((int)(__ffs(m) - 1) == lane) atomicAdd(&hist[bin], __popc(m));
    }
    __syncthreads();
    find_threshold(hist, KTOP, tid, lane, wid, sscan, &sT1, &sH, &sG1);
    const int T1 = sT1;
    unsigned thr = (unsigned)T1 << 21;
    int total = sG1 + sH;

    if (total > 1024) {
        // level 2: bits [20:10] within bin T1
        for (int i = tid; i < 2048; i += nt) hist[i] = 0;
        __syncthreads();
#pragma unroll
        for (int it = 0; it < NIT; it++) {
            bool v = ((int)(bits[it] >> 21) == T1);
            int sub = (int)((bits[it] >> 10) & 2047);
            unsigned bal = __ballot_sync(0xFFFFFFFFu, v);
            if (v) {
                unsigned m = __match_any_sync(bal, sub);
                if ((int)(__ffs(m) - 1) == lane) atomicAdd(&hist[sub], __popc(m));
            }
        }
        __syncthreads();
        find_threshold(hist, KTOP - sG1, tid, lane, wid, sscan, &sT2, &sH, &sG2);
        thr |= (unsigned)sT2 << 10;
        total = sG1 + sG2 + sH;

        if (total > 1024) {
            // level 3: low 10 bits within (T1,T2)
            unsigned pre = thr >> 10;
            for (int i = tid; i < 2048; i += nt) hist[i] = 0;
            __syncthreads();
#pragma unroll
            for (int it = 0; it < NIT; it++) {
                bool v = ((bits[it] >> 10) == pre);
                int low = (int)(bits[it] & 1023);
                unsigned bal = __ballot_sync(0xFFFFFFFFu, v);
                if (v) {
                    unsigned m = __match_any_sync(bal, low);
                    if ((int)(__ffs(m) - 1) == lane) atomicAdd(&hist[low], __popc(m));
                }
            }
            __syncthreads();
            find_threshold(hist, KTOP - sG1 - sG2, tid, lane, wid, sscan,
                           &sT3, &sH, &sG3);
            thr |= (unsigned)sT3;
        }
    }
    if (tid == 0) csel = 0;
    __syncthreads();

    // single compaction: selected iff bits >= thr
#pragma unroll
    for (int it = 0; it < NIT; it++) {
        int p = tid + it * nt;
        bool sel = (p < PP) && (bits[it] >= thr);
        unsigned long long key = ((unsigned long long)bits[it] << 32) |
                                 (unsigned long long)(0xFFFFFFFFu - (unsigned)p);
        unsigned bd = __ballot_sync(0xFFFFFFFFu, sel);
        if (bd) {
            int ldr = __ffs(bd) - 1, base = 0;
            if (lane == ldr) base = atomicAdd(&csel, __popc(bd));
            base = __shfl_sync(0xFFFFFFFFu, base, ldr);
            if (sel) {
                int pos = base + __popc(bd & lmask);
                if (pos < 1024) selkeys[pos] = key;
            }
        }
    }
    __syncthreads();
    if (tid >= min(csel, 1024)) selkeys[tid] = 0ULL;
    __syncthreads();
    sort1024_desc(selkeys, tid);

    // emit sc / bx / selidx / default keep + keep bitmask; batch box max
    float* osc = out;
    float* obx = out + 2 * BB * KTOP;
    float* okp = out + 6 * BB * KTOP;
    unsigned long long key = selkeys[tid];
    float s = __uint_as_float((unsigned)(key >> 32));
    bool kp = (tid < KTOP) && (s >= 0.05f);
    unsigned kb = __ballot_sync(0xFFFFFFFFu, kp);
    if (lane == 0) g_keepbits[b * 32 + wid] = kb;

    float localmax = -1e30f;
    if (tid < KTOP) {
        unsigned idx = 0xFFFFFFFFu - (unsigned)(key & 0xFFFFFFFFu);
        if (idx >= PP) idx = 0;
        float4 bx = g_box[b * PP + (int)idx];
        osc[b * KTOP + tid] = s;
        ((float4*)obx)[b * KTOP + tid] = bx;
        g_selidx[b * KTOP + tid] = (int)idx;
        okp[b * KTOP + tid] = kp ? 1.0f : 0.0f;
        localmax = fmaxf(fmaxf(bx.x, bx.y), fmaxf(bx.z, bx.w));
    }
#pragma unroll
    for (int o = 16; o > 0; o >>= 1)
        localmax = fmaxf(localmax, __shfl_xor_sync(0xFFFFFFFFu, localmax, o));
    if (lane == 0) swmax[wid] = localmax;
    __syncthreads();
    if (wid == 0) {
        float m = swmax[lane];
#pragma unroll
        for (int o = 16; o > 0; o >>= 1)
            m = fmaxf(m, __shfl_xor_sync(0xFFFFFFFFu, m, o));
        if (lane == 0) g_mx[b] = m;
    }
}

// ---------------- kernel 3: full-chip argmax over sigmoid (selected) ---------
__global__ __launch_bounds__(256) void argmax_kernel(Ptrs ps, float* out) {
    int g = blockIdx.x * 8 + (threadIdx.x >> 5);   // one warp per selected point
    const int lane = threadIdx.x & 31;
    if (g >= BB * KTOP) return;
    int b = g / KTOP, i = g - b * KTOP;
    int p = g_selidx[g];
    int lvl, start, HW, W, S;
    level_of(p, lvl, start, HW, W, S);
    int local = p - start;
    const float* base = ps.cls[lvl] + (long)(b * NCLS) * HW + local;

    float l0 = base[(long)lane * HW];
    float l1 = base[(long)(lane + 32) * HW];
    float l2 = (lane < 16) ? base[(long)(lane + 64) * HW] : 0.0f;

    float bestS = xla_sigmoid(l0); int bestC = lane;
    float s1 = xla_sigmoid(l1);
    if (s1 > bestS) { bestS = s1; bestC = lane + 32; }
    if (lane < 16) {
        float s2 = xla_sigmoid(l2);
        if (s2 > bestS) { bestS = s2; bestC = lane + 64; }
    }
#pragma unroll
    for (int o = 16; o > 0; o >>= 1) {
        float oS = __shfl_xor_sync(0xFFFFFFFFu, bestS, o);
        int   oC = __shfl_xor_sync(0xFFFFFFFFu, bestC, o);
        if (oS > bestS || (oS == bestS && oC < bestC)) { bestS = oS; bestC = oC; }
    }
    if (lane == 0) {
        out[BB * KTOP + b * KTOP + i] = (float)(bestC + 1);         // ocl
        // transposed class byte: lane (i&31) byte (i>>5)
        g_cls8[b * 1024 + (i & 31) * 32 + (i >> 5)] = (unsigned char)(bestC + 1);
    }
}

// ---------------- kernel 4: warp-per-(batch,class) NMS, zero smem ------------
// One warp per (b,c) pair. Lane l holds class bytes of ranks {s*32+l} in 8 regs
// (transposed layout: 2x LDG.128). Round s: class byte is a compile-time byte
// extract; keep bit via one shfl. No shared memory on the fast path.
__global__ __launch_bounds__(256) void nms_kernel(float* out) {
    const int tid = threadIdx.x, lane = tid & 31, wid = tid >> 5;
    const unsigned lmask = (1u << lane) - 1u;
    const int pair = blockIdx.x * 8 + wid;      // 0..2559
    const int b = pair / NCLS, c = pair - b * NCLS;
    const float* obx = out + 2 * BB * KTOP;
    float* okp = out + 6 * BB * KTOP;

    const unsigned cc4 = (unsigned)(c + 1) * 0x01010101u;  // replicated byte
    const unsigned kw = g_keepbits[b * 32 + lane];

    // lane's 32 class bytes (ranks s*32+lane, s=0..31), contiguous in memory
    const uint4* clsv = (const uint4*)(g_cls8 + b * 1024 + lane * 32);
    uint4 w0 = clsv[0], w1 = clsv[1];
    unsigned cw[8] = { w0.x, w0.y, w0.z, w0.w, w1.x, w1.y, w1.z, w1.w };

    // enumerate candidates in rank order; lane t receives candidate t's rank
    int nk = 0, myrank = -1;
#pragma unroll
    for (int s = 0; s < 32; s++) {
        unsigned kws = __shfl_sync(0xFFFFFFFFu, kw, s);
        unsigned byte = (cw[s >> 2] >> ((s & 3) * 8)) & 0xFFu;
        bool cd = (((kws >> lane) & 1u) != 0u) && (byte * 0x01010101u == cc4);
        unsigned bal = __ballot_sync(0xFFFFFFFFu, cd);
        int cnt = __popc(bal);
        int rel = lane - nk;
        if (rel >= 0 && rel < cnt) myrank = s * 32 + (int)__fns(bal, 0, rel + 1);
        nk += cnt;
    }
    const int n = nk;
    if (n <= 1) return;   // default keep already written by topk

    const float m1 = __fadd_rn(g_mx[b], 1.0f);
    const float off = __fmul_rn(m1, (float)(c + 1));

    if (n <= 32) {
        // register-resident greedy: lane t holds candidate t
        int myr = (lane < n) ? myrank : -1;
        float bx1 = 0, by1 = 0, bx2 = 0, by2 = 0, ba = 0;
        if (myr >= 0) {
            float4 bb = ((const float4*)obx)[b * KTOP + myr];
            bx1 = __fadd_rn(bb.x, off); by1 = __fadd_rn(bb.y, off);
            bx2 = __fadd_rn(bb.z, off); by2 = __fadd_rn(bb.w, off);
            ba = __fmul_rn(fmaxf(__fsub_rn(bx2, bx1), 0.f),
                           fmaxf(__fsub_rn(by2, by1), 0.f));
        }
        bool mykeep = false;
        for (int t = 0; t < n; t++) {
            float tx1 = __shfl_sync(0xFFFFFFFFu, bx1, t);
            float ty1 = __shfl_sync(0xFFFFFFFFu, by1, t);
            float tx2 = __shfl_sync(0xFFFFFFFFu, bx2, t);
            float ty2 = __shfl_sync(0xFFFFFFFFu, by2, t);
            float ta  = __shfl_sync(0xFFFFFFFFu, ba, t);
            bool mysup = false;
            if (mykeep) {   // lane kept and lane < t by construction
                float xx1 = fmaxf(bx1, tx1), yy1 = fmaxf(by1, ty1);
                float xx2 = fminf(bx2, tx2), yy2 = fminf(by2, ty2);
                float w = fmaxf(__fsub_rn(xx2, xx1), 0.f);
                float h = fmaxf(__fsub_rn(yy2, yy1), 0.f);
                float inter = __fmul_rn(w, h);
                float den = __fadd_rn(
                    __fsub_rn(__fadd_rn(ba, ta), inter), 1e-9f);
                mysup = (__fdiv_rn(inter, den) > 0.6f);
            }
            bool sup = __any_sync(0xFFFFFFFFu, mysup);
            if (lane == t) mykeep = !sup;
        }
        if (myr >= 0 && !mykeep) okp[b * KTOP + myr] = 0.0f;
        return;
    }

    // fallback (rare, n>32): enumerate ranks into global scratch, chunked greedy
    {
        short* fcl = g_fclist + pair * KTOP;
        short* fkl = g_fklist + pair * KTOP;
        int pos = 0;
#pragma unroll
        for (int s = 0; s < 32; s++) {
            unsigned kws = __shfl_sync(0xFFFFFFFFu, kw, s);
            unsigned byte = (cw[s >> 2] >> ((s & 3) * 8)) & 0xFFu;
            bool cd = (((kws >> lane) & 1u) != 0u) && (byte * 0x01010101u == cc4);
            unsigned bal = __ballot_sync(0xFFFFFFFFu, cd);
            if (cd) fcl[pos + __popc(bal & lmask)] = (short)(s * 32 + lane);
            pos += __popc(bal);
        }
        __syncwarp();
        int nkk = 0;
        for (int t = 0; t < n; t++) {
            int r = (int)fcl[t];
            float4 bbt = ((const float4*)obx)[b * KTOP + r];
            float ax1 = __fadd_rn(bbt.x, off), ay1 = __fadd_rn(bbt.y, off);
            float ax2 = __fadd_rn(bbt.z, off), ay2 = __fadd_rn(bbt.w, off);
            float aa = __fmul_rn(fmaxf(__fsub_rn(ax2, ax1), 0.f),
                                 fmaxf(__fsub_rn(ay2, ay1), 0.f));
            bool sup = false;
            for (int kb = 0; kb < nkk && !sup; kb += 32) {
                int kk = kb + lane;
                bool mysup = false;
                if (kk < nkk) {
                    int j = (int)fkl[kk];
                    float4 bbj = ((const float4*)obx)[b * KTOP + j];
                    float jx1 = __fadd_rn(bbj.x, off), jy1 = __fadd_rn(bbj.y, off);
                    float jx2 = __fadd_rn(bbj.z, off), jy2 = __fadd_rn(bbj.w, off);
                    float ja = __fmul_rn(fmaxf(__fsub_rn(jx2, jx1), 0.f),
                                         fmaxf(__fsub_rn(jy2, jy1), 0.f));
                    float xx1 = fmaxf(ax1, jx1), yy1 = fmaxf(ay1, jy1);
                    float xx2 = fminf(ax2, jx2), yy2 = fminf(ay2, jy2);
                    float w = fmaxf(__fsub_rn(xx2, xx1), 0.f);
                    float h = fmaxf(__fsub_rn(yy2, yy1), 0.f);
                    float inter = __fmul_rn(w, h);
                    float den = __fadd_rn(
                        __fsub_rn(__fadd_rn(aa, ja), inter), 1e-9f);
                    mysup = (__fdiv_rn(inter, den) > 0.6f);
                }
                if (__any_sync(0xFFFFFFFFu, mysup)) sup = true;
            }
            if (sup) {
                if (lane == 0) okp[b * KTOP + r] = 0.0f;
            } else {
                if (lane == 0) fkl[nkk] = (short)r;
                nkk++;
            }
            __syncwarp();
        }
    }
}

// ---------------- launch ------------------------------------------------------
extern "C" void kernel_launch(void* const* d_in, const int* in_sizes, int n_in,
                              void* d_out, int out_size) {
    Ptrs ps;
    for (int i = 0; i < 5; i++) {
        ps.cls[i] = (const float*)d_in[i];
        ps.cen[i] = (const float*)d_in[5 + i];
        ps.reg[i] = (const float*)d_in[10 + i];
    }
    const int Q = (BB * PP) / 4;
    float* out = (float*)d_out;
    score_kernel<<<(Q + 255) / 256, 256>>>(ps);
    topk_kernel<<<BB, 1024>>>(out);
    argmax_kernel<<<(BB * KTOP + 7) / 8, 256>>>(ps, out);
    nms_kernel<<<(BB * NCLS) / 8, 256>>>(out);
}